// round 1
// baseline (speedup 1.0000x reference)
#include <cuda_runtime.h>
#include <stdint.h>

#define D_DIM   10000
#define T_STEPS 2048
#define TN      (T_STEPS - 2)   /* 2046 ngram terms */
#define NCH     4

#define W4        124           /* output columns advanced per group (window=128) */
#define G_GROUPS  81            /* ceil(10000 / 124) */
#define S_CHUNKS  30
#define CHUNK     69            /* ceil(2046 / 30) */

__device__ int   g_idxpack[T_STEPS];
__device__ float g_sample[D_DIM];

/* CHOSEN_FEAT - 1 (index into feat[]) */
__constant__ int c_featIdx[29] = {
    546,547,548,550,553,555,556,557,558,559,560,561,562,564,
    565,566,569,575,579,580,581,582,583,584,587,592,597,598,599
};

/* ---------- kernel 1: zero accumulator + pack level indices ---------- */
__global__ void k_init(const float* __restrict__ signals)
{
    int i = blockIdx.x * blockDim.x + threadIdx.x;
    if (i < D_DIM) g_sample[i] = 0.0f;
    if (i < T_STEPS) {
        int pack = 0;
#pragma unroll
        for (int c = 0; c < NCH; ++c) {
            float s = signals[i * NCH + c];
            s = fminf(fmaxf(s, 0.0f), 1.0f);
            int l = (int)rintf(s * 99.0f);      /* round-half-even == jnp.round */
            l = min(max(l, 0), 99);
            pack |= l << (8 * c);
        }
        g_idxpack[i] = pack;
    }
}

/* ---------- kernel 2: per_t + ngram + multiset sum ---------- */
__global__ void __launch_bounds__(128) k_ngram(const float* __restrict__ keys,
                                               const float* __restrict__ lw)
{
    const int warpId = threadIdx.x >> 5;
    const int lane   = threadIdx.x & 31;
    const int unit   = blockIdx.x * 4 + warpId;
    if (unit >= G_GROUPS * S_CHUNKS) return;
    const int g  = unit % G_GROUPS;
    const int s  = unit / G_GROUPS;
    const int i0 = s * CHUNK;
    const int i1 = min(i0 + CHUNK, TN);
    if (i0 >= i1) return;

    /* lane owns 4 consecutive per_t columns of this group's 128-col window */
    int c0 = g * W4 + 4 * lane;
    if (c0 >= D_DIM) c0 -= D_DIM;          /* only group 80 wraps; stays 4-aligned */

    const float4 k0 = *(const float4*)(keys + 0 * D_DIM + c0);
    const float4 k1 = *(const float4*)(keys + 1 * D_DIM + c0);
    const float4 k2 = *(const float4*)(keys + 2 * D_DIM + c0);
    const float4 k3 = *(const float4*)(keys + 3 * D_DIM + c0);
    const float* lwc = lw + c0;

    /* one time-step: compute per_t for 4 columns, build d-1 / d-2 shifted views */
    auto step = [&](int t, float4& s1, float4& s2) -> float4 {
        const int pk = g_idxpack[t];
        const float4 e0 = *(const float4*)(lwc + (pk & 255) * D_DIM);
        const float4 e1 = *(const float4*)(lwc + ((pk >> 8)  & 255) * D_DIM);
        const float4 e2 = *(const float4*)(lwc + ((pk >> 16) & 255) * D_DIM);
        const float4 e3 = *(const float4*)(lwc + ((pk >> 24) & 255) * D_DIM);
        float4 v;
        v.x = k0.x*e0.x + k1.x*e1.x + k2.x*e2.x + k3.x*e3.x;
        v.y = k0.y*e0.y + k1.y*e1.y + k2.y*e2.y + k3.y*e3.y;
        v.z = k0.z*e0.z + k1.z*e1.z + k2.z*e2.z + k3.z*e3.z;
        v.w = k0.w*e0.w + k1.w*e1.w + k2.w*e2.w + k3.w*e3.w;
        const float n3 = __shfl_up_sync(0xffffffffu, v.w, 1);  /* prev lane col+3 */
        const float n2 = __shfl_up_sync(0xffffffffu, v.z, 1);  /* prev lane col+2 */
        s1 = make_float4(n3, v.x, v.y, v.z);   /* per_t[t, p-1] */
        s2 = make_float4(n2, n3, v.x, v.y);    /* per_t[t, p-2] */
        return v;
    };

    float4 acc = make_float4(0.f, 0.f, 0.f, 0.f);

    /* warm-up: fill the 2-deep delay line */
    float4 sA1, sA2, sB1, sB2, sc1, sc2;
    (void)step(i0,     sA1, sA2);   /* s2 @ t-2 */
    (void)step(i0 + 1, sB1, sB2);   /* s1 @ t-1 (and its s2 for the shift) */

    for (int t = i0 + 2; t < i1 + 2; ++t) {
        const float4 v = step(t, sc1, sc2);
        acc.x += sA2.x * sB1.x * v.x;
        acc.y += sA2.y * sB1.y * v.y;
        acc.z += sA2.z * sB1.z * v.z;
        acc.w += sA2.w * sB1.w * v.w;
        sA2 = sB2; sB2 = sc2; sB1 = sc1;
    }

    /* write back: window positions 2..125, global output cap at wrap */
#pragma unroll
    for (int e = 0; e < 4; ++e) {
        const int p = 4 * lane + e;
        if (p < 2) continue;
        int o = g * W4 + p;
        if (o > D_DIM + 1) continue;           /* dedupe wrap overlap */
        if (o >= D_DIM) o -= D_DIM;
        const float a = (e == 0) ? acc.x : (e == 1) ? acc.y : (e == 2) ? acc.z : acc.w;
        atomicAdd(&g_sample[o], a);            /* exact integers: order-independent */
    }
}

/* ---------- kernel 3: feat/MFCC sinusoid kernels + combine + sign ---------- */
__global__ void __launch_bounds__(256) k_combine(const float* __restrict__ feat,
                                                 const float* __restrict__ feat_w,
                                                 const float* __restrict__ feat_b,
                                                 const float* __restrict__ mfcc_w,
                                                 const float* __restrict__ mfcc_b,
                                                 float* __restrict__ out)
{
    __shared__ float s_feat[600];
    __shared__ float s_fh[8][32];
    const int tid = threadIdx.x;
    for (int i = tid; i < 600; i += 256) s_feat[i] = feat[i];
    __syncthreads();

    const int warpId = tid >> 5;
    const int lane   = tid & 31;
    const int d      = blockIdx.x * 8 + warpId;
    if (d >= D_DIM) return;

    /* MFCC: 6 warp-cooperative 91-length dots (coalesced), multibind product */
    float prod = 1.0f;
#pragma unroll
    for (int k = 0; k < 6; ++k) {
        const float* wrow = mfcc_w + (k * D_DIM + d) * 91;
        float a = 0.0f;
        if (lane < 27) a += wrow[64 + lane] * s_feat[k * 91 + 64 + lane];
        a += wrow[32 + lane] * s_feat[k * 91 + 32 + lane];
        a += wrow[lane]      * s_feat[k * 91 + lane];
#pragma unroll
        for (int off = 16; off; off >>= 1) a += __shfl_xor_sync(0xffffffffu, a, off);
        const float b = mfcc_b[k * D_DIM + d];
        prod *= cosf(a + b) * sinf(a);
    }

    /* 29 scalar sinusoid feature HVs: one per lane */
    float fh = 0.0f;
    if (lane < 29) {
        const float sv = s_feat[c_featIdx[lane]];
        const float pw = sv * feat_w[lane * D_DIM + d];
        fh = cosf(pw + feat_b[lane * D_DIM + d]) * sinf(pw);
    }
    s_fh[warpId][lane] = fh;
    __syncwarp();

    if (lane == 0) {
        const float* f = s_fh[warpId];
        const float comb =
              f[0]  * f[8]  * f[13]
            + f[1]  * f[9]  * f[14]
            + f[2]  * f[10] * f[15]
            + f[3]  * f[4]
            + f[5]  * f[7]  * f[22] * f[6]  * f[23] * f[19] * f[18]
                    * f[20] * f[21] * f[26] * f[28] * f[27]
            + f[11] + f[12]
            + f[16] * f[24]
            + f[17] + f[25]
            + prod;
        const float sv = g_sample[d] * comb;
        out[d] = (sv > 0.0f) ? 1.0f : -1.0f;
    }
}

/* ---------- launcher ---------- */
extern "C" void kernel_launch(void* const* d_in, const int* in_sizes, int n_in,
                              void* d_out, int out_size)
{
    (void)in_sizes; (void)n_in; (void)out_size;
    const float* signals = (const float*)d_in[0];
    const float* feat    = (const float*)d_in[1];
    const float* keys    = (const float*)d_in[2];
    const float* lw      = (const float*)d_in[3];
    const float* fw      = (const float*)d_in[4];
    const float* fb      = (const float*)d_in[5];
    const float* mw      = (const float*)d_in[6];
    const float* mb      = (const float*)d_in[7];
    float* out = (float*)d_out;

    k_init<<<40, 256>>>(signals);
    k_ngram<<<(G_GROUPS * S_CHUNKS + 3) / 4, 128>>>(keys, lw);
    k_combine<<<1250, 256>>>(feat, fw, fb, mw, mb, out);
}

// round 3
// speedup vs baseline: 1.1319x; 1.1319x over previous
#include <cuda_runtime.h>
#include <stdint.h>

#define D_DIM   10000
#define T_STEPS 2048
#define TN      2046            /* ngram terms */
#define ROWPW   2512            /* padded table row: 10048 cols = 2512 words */
#define GROUPS  81              /* column groups, stride 124, window 128 */
#define SSPLIT  6               /* t-splits per group */
#define TCHUNK  341             /* 2046 / 6 */
#define WCH     22              /* ceil(341/16) steps per warp */
#define SMEM_BYTES (12800*4 + 128*4)

/* signed tables: plane c, row l, padded 10048 cols (cols>=10000 mirror 0..47) */
__device__ uint32_t g_tab[4 * 100 * ROWPW];       /* ~4.02 MB */
__device__ uint4    g_idx4[T_STEPS];              /* per-t smem word offsets, 4 channels */
__device__ float    g_sample[D_DIM];

__constant__ int c_featIdx[29] = {
    546,547,548,550,553,555,556,557,558,559,560,561,562,564,
    565,566,569,575,579,580,581,582,583,584,587,592,597,598,599
};

/* ---------- kernel 1: zero acc + pack level offsets + build signed int8 tables ---------- */
__global__ void __launch_bounds__(256) k_init(const float* __restrict__ signals,
                                              const float* __restrict__ keys,
                                              const float* __restrict__ lw)
{
    const int i = blockIdx.x * blockDim.x + threadIdx.x;

    if (i < D_DIM) g_sample[i] = 0.0f;

    if (i < T_STEPS) {
        int l[4];
#pragma unroll
        for (int c = 0; c < 4; ++c) {
            float s = signals[i * 4 + c];
            s = fminf(fmaxf(s, 0.0f), 1.0f);
            int v = (int)rintf(s * 99.0f);        /* round-half-even == jnp.round */
            l[c] = min(max(v, 0), 99);
        }
        /* word offsets into s_tab: plane stride 3200 words, row stride 32 words */
        g_idx4[i] = make_uint4(l[0]*32, 3200 + l[1]*32, 6400 + l[2]*32, 9600 + l[3]*32);
    }

    /* table prep: one thread per (row l, 4-col word) handles all 4 channels */
    if (i < 100 * ROWPW) {
        const int w    = i % ROWPW;
        const int lrow = i / ROWPW;
        const int dd   = w * 4;
        const int dsrc = (dd >= D_DIM) ? dd - D_DIM : dd;
        const float4 wf = *(const float4*)(lw + lrow * D_DIM + dsrc);
#pragma unroll
        for (int c = 0; c < 4; ++c) {
            const float4 kf = *(const float4*)(keys + c * D_DIM + dsrc);
            uint32_t p;
            uint32_t b0 = (kf.x * wf.x > 0.f) ? 0x01u : 0xFFu;
            uint32_t b1 = (kf.y * wf.y > 0.f) ? 0x01u : 0xFFu;
            uint32_t b2 = (kf.z * wf.z > 0.f) ? 0x01u : 0xFFu;
            uint32_t b3 = (kf.w * wf.w > 0.f) ? 0x01u : 0xFFu;
            p = b0 | (b1 << 8) | (b2 << 16) | (b3 << 24);
            g_tab[(c * 100 + lrow) * ROWPW + w] = p;
        }
    }
}

/* ---------- kernel 2: per_t + ngram + multiset sum (int8/SMEM path) ---------- */
__global__ void __launch_bounds__(512) k_ngram()
{
    extern __shared__ uint32_t smem[];
    uint32_t* s_tab = smem;                 /* 12800 words = 4 planes x 100 x 32 */
    int*      s_acc = (int*)(smem + 12800); /* 128 per-window-column accumulators */

    const int tid  = threadIdx.x;
    const int g    = blockIdx.x / SSPLIT;
    const int s    = blockIdx.x % SSPLIT;
    const int gw   = g * 31;                /* window start, words */

    /* stage window: 400 rows x 32 words, coalesced */
    for (int w = tid; w < 12800; w += 512) {
        const int row = w >> 5;
        s_tab[w] = g_tab[row * ROWPW + gw + (w & 31)];
    }
    if (tid < 128) s_acc[tid] = 0;
    __syncthreads();

    const int warp = tid >> 5;
    const int lane = tid & 31;
    const int t0 = s * TCHUNK + warp * WCH;
    const int t1 = min(t0 + WCH, (s + 1) * TCHUNK);

    if (t0 < t1) {
        int a2x, a2y, a2z, a2w;             /* s2 @ t-2 */
        int b2x, b2y, b2z, b2w;             /* s2 @ t-1 */
        int b1x, b1y, b1z, b1w;             /* s1 @ t-1 */
        int ax = 0, ay = 0, az = 0, aw = 0; /* accumulators */

#define NG_STEP(ROW, V0,V1,V2,V3, S1X,S1Y,S1Z,S1W, S2X,S2Y,S2Z,S2W)            \
        {                                                                       \
            const uint4 ix = g_idx4[ROW];                                       \
            const uint32_t u0 = s_tab[ix.x + lane];                             \
            const uint32_t u1 = s_tab[ix.y + lane];                             \
            const uint32_t u2 = s_tab[ix.z + lane];                             \
            const uint32_t u3 = s_tab[ix.w + lane];                             \
            const uint32_t sm = __vadd4(__vadd4(u0, u1), __vadd4(u2, u3));      \
            V0 = __dp4a((int)sm, 0x00000001, 0);                                \
            V1 = __dp4a((int)sm, 0x00000100, 0);                                \
            V2 = __dp4a((int)sm, 0x00010000, 0);                                \
            V3 = __dp4a((int)sm, 0x01000000, 0);                                \
            const int n3 = __shfl_up_sync(0xffffffffu, V3, 1);                  \
            const int n2 = __shfl_up_sync(0xffffffffu, V2, 1);                  \
            S1X = n3; S1Y = V0; S1Z = V1; S1W = V2;                             \
            S2X = n2; S2Y = n3; S2Z = V0; S2W = V1;                             \
        }

        {   /* warm-up rows t0, t0+1 */
            int v0,v1,v2,v3, d1x,d1y,d1z,d1w;
            NG_STEP(t0,     v0,v1,v2,v3, d1x,d1y,d1z,d1w, a2x,a2y,a2z,a2w);
            NG_STEP(t0 + 1, v0,v1,v2,v3, b1x,b1y,b1z,b1w, b2x,b2y,b2z,b2w);
        }

        for (int t = t0 + 2; t < t1 + 2; ++t) {
            int v0,v1,v2,v3, c1x,c1y,c1z,c1w, c2x,c2y,c2z,c2w;
            NG_STEP(t, v0,v1,v2,v3, c1x,c1y,c1z,c1w, c2x,c2y,c2z,c2w);
            ax += a2x * b1x * v0;
            ay += a2y * b1y * v1;
            az += a2z * b1z * v2;
            aw += a2w * b1w * v3;
            a2x = b2x; a2y = b2y; a2z = b2z; a2w = b2w;
            b2x = c2x; b2y = c2y; b2z = c2z; b2w = c2w;
            b1x = c1x; b1y = c1y; b1z = c1z; b1w = c1w;
        }
#undef NG_STEP

        atomicAdd(&s_acc[4*lane + 0], ax);
        atomicAdd(&s_acc[4*lane + 1], ay);
        atomicAdd(&s_acc[4*lane + 2], az);
        atomicAdd(&s_acc[4*lane + 3], aw);
    }

    __syncthreads();
    /* window positions 2..125 -> global (wrap group keeps o <= D+1) */
    if (tid >= 2 && tid < 126) {
        int o = g * 124 + tid;
        if (o <= D_DIM + 1) {
            if (o >= D_DIM) o -= D_DIM;
            atomicAdd(&g_sample[o], (float)s_acc[tid]);
        }
    }
}

/* ---------- kernel 3: feat/MFCC sinusoid kernels + combine + sign ---------- */
__global__ void __launch_bounds__(256) k_combine(const float* __restrict__ feat,
                                                 const float* __restrict__ feat_w,
                                                 const float* __restrict__ feat_b,
                                                 const float* __restrict__ mfcc_w,
                                                 const float* __restrict__ mfcc_b,
                                                 float* __restrict__ out)
{
    __shared__ float s_feat[600];
    __shared__ float s_fh[8][32];
    const int tid = threadIdx.x;
    for (int i = tid; i < 600; i += 256) s_feat[i] = feat[i];
    __syncthreads();

    const int warpId = tid >> 5;
    const int lane   = tid & 31;
    const int d      = blockIdx.x * 8 + warpId;
    if (d >= D_DIM) return;

    float prod = 1.0f;
#pragma unroll
    for (int k = 0; k < 6; ++k) {
        const float* wrow = mfcc_w + (k * D_DIM + d) * 91;
        float a = 0.0f;
        if (lane < 27) a += wrow[64 + lane] * s_feat[k * 91 + 64 + lane];
        a += wrow[32 + lane] * s_feat[k * 91 + 32 + lane];
        a += wrow[lane]      * s_feat[k * 91 + lane];
#pragma unroll
        for (int off = 16; off; off >>= 1) a += __shfl_xor_sync(0xffffffffu, a, off);
        const float b = mfcc_b[k * D_DIM + d];
        prod *= cosf(a + b) * sinf(a);
    }

    float fh = 0.0f;
    if (lane < 29) {
        const float sv = s_feat[c_featIdx[lane]];
        const float pw = sv * feat_w[lane * D_DIM + d];
        fh = cosf(pw + feat_b[lane * D_DIM + d]) * sinf(pw);
    }
    s_fh[warpId][lane] = fh;
    __syncwarp();

    if (lane == 0) {
        const float* f = s_fh[warpId];
        const float comb =
              f[0]  * f[8]  * f[13]
            + f[1]  * f[9]  * f[14]
            + f[2]  * f[10] * f[15]
            + f[3]  * f[4]
            + f[5]  * f[7]  * f[22] * f[6]  * f[23] * f[19] * f[18]
                    * f[20] * f[21] * f[26] * f[28] * f[27]
            + f[11] + f[12]
            + f[16] * f[24]
            + f[17] + f[25]
            + prod;
        const float sv = g_sample[d] * comb;
        out[d] = (sv > 0.0f) ? 1.0f : -1.0f;
    }
}

/* ---------- launcher ---------- */
extern "C" void kernel_launch(void* const* d_in, const int* in_sizes, int n_in,
                              void* d_out, int out_size)
{
    (void)in_sizes; (void)n_in; (void)out_size;
    const float* signals = (const float*)d_in[0];
    const float* feat    = (const float*)d_in[1];
    const float* keys    = (const float*)d_in[2];
    const float* lw      = (const float*)d_in[3];
    const float* fw      = (const float*)d_in[4];
    const float* fb      = (const float*)d_in[5];
    const float* mw      = (const float*)d_in[6];
    const float* mb      = (const float*)d_in[7];
    float* out = (float*)d_out;

    cudaFuncSetAttribute(k_ngram, cudaFuncAttributeMaxDynamicSharedMemorySize, SMEM_BYTES);

    k_init<<<(100 * ROWPW + 255) / 256, 256>>>(signals, keys, lw);
    k_ngram<<<GROUPS * SSPLIT, 512, SMEM_BYTES>>>();
    k_combine<<<1250, 256>>>(feat, fw, fb, mw, mb, out);
}